// round 14
// baseline (speedup 1.0000x reference)
#include <cuda_runtime.h>
#include <cuda_fp16.h>
#include <cstdint>

// q,k,v: [B=4,H=16,S=2048,D=64] fp32. out = [B,H,S,D] then attn [B,H,S,S] (fp32).
#define SEQ   2048
#define HDIM  64
#define NBH   64
#define QTILE 128
#define TKEY  128
#define NTILES (SEQ/TKEY)
#define NQT   (SEQ/QTILE)
#define NTHREADS 256

// fold 1/temperature (1/8) and log2(e) into Q: softmax runs in exp2 domain
#define QSCALE (1.4426950408889634f / 8.0f)

// preconverted fp16 operands
__device__ __half g_qh[(size_t)NBH * SEQ * HDIM];
__device__ __half g_kh[(size_t)NBH * SEQ * HDIM];
__device__ __half g_vth[(size_t)NBH * HDIM * SEQ];   // V^T [bh][d][s]
__device__ float g_inv[(size_t)NBH * SEQ];           // per-row 1/sum
// unnormalized P = exp2(scores) in fp16, fragment-identity layout:
// index = ((cta * NTILES + kt) * 4096) + nbb * 256 + tid   (uint2 = 2x half2)
__device__ uint2 g_p[(size_t)NBH * NQT * NTILES * 4096];

// ---------------------------------------------------------------------------
__device__ __forceinline__ uint32_t smem_u32(const void* p) {
    uint32_t a;
    asm("{ .reg .u64 t; cvta.to.shared.u64 t, %1; cvt.u32.u64 %0, t; }" : "=r"(a) : "l"(p));
    return a;
}
__device__ __forceinline__ void ldm4(uint32_t* r, uint32_t a) {
    asm volatile("ldmatrix.sync.aligned.m8n8.x4.shared.b16 {%0,%1,%2,%3}, [%4];"
                 : "=r"(r[0]), "=r"(r[1]), "=r"(r[2]), "=r"(r[3]) : "r"(a));
}
__device__ __forceinline__ void mma16816(float* c, const uint32_t* a, const uint32_t* b) {
    asm volatile("mma.sync.aligned.m16n8k16.row.col.f32.f16.f16.f32 "
                 "{%0,%1,%2,%3},{%4,%5,%6,%7},{%8,%9},{%0,%1,%2,%3};"
                 : "+f"(c[0]), "+f"(c[1]), "+f"(c[2]), "+f"(c[3])
                 : "r"(a[0]), "r"(a[1]), "r"(a[2]), "r"(a[3]), "r"(b[0]), "r"(b[1]));
}
__device__ __forceinline__ uint32_t pack_h2(float a, float b) {
    __half2 h = __floats2half2_rn(a, b);
    return *reinterpret_cast<uint32_t*>(&h);
}

// ---- packed f32x2 ops (Blackwell FFMA2 path) --------------------------------
__device__ __forceinline__ uint64_t pk2(float a, float b) {
    uint64_t r; asm("mov.b64 %0,{%1,%2};" : "=l"(r) : "f"(a), "f"(b)); return r;
}
__device__ __forceinline__ uint64_t dup2(float c) {
    uint64_t r; asm("mov.b64 %0,{%1,%1};" : "=l"(r) : "f"(c)); return r;
}
__device__ __forceinline__ uint64_t add2(uint64_t a, uint64_t b) {
    uint64_t r; asm("add.rn.f32x2 %0,%1,%2;" : "=l"(r) : "l"(a), "l"(b)); return r;
}
__device__ __forceinline__ uint64_t mul2(uint64_t a, uint64_t b) {
    uint64_t r; asm("mul.rn.f32x2 %0,%1,%2;" : "=l"(r) : "l"(a), "l"(b)); return r;
}
__device__ __forceinline__ uint64_t fma2(uint64_t a, uint64_t b, uint64_t c) {
    uint64_t r; asm("fma.rn.f32x2 %0,%1,%2,%3;" : "=l"(r) : "l"(a), "l"(b), "l"(c)); return r;
}
__device__ __forceinline__ float lo2(uint64_t v) { return __uint_as_float((uint32_t)v); }
__device__ __forceinline__ float hi2(uint64_t v) { return __uint_as_float((uint32_t)(v >> 32)); }

// packed exp2 constants
struct ExpC {
    uint64_t C, N1, p5, p4, p3, p2, p1, p0;
};
__device__ __forceinline__ ExpC make_expc() {
    ExpC e;
    e.C  = dup2(12582912.0f);
    e.N1 = dup2(-1.0f);
    e.p5 = dup2(1.3333558146428443e-3f);
    e.p4 = dup2(9.6181291076284772e-3f);
    e.p3 = dup2(5.5504108664821580e-2f);
    e.p2 = dup2(2.4022650695910072e-1f);
    e.p1 = dup2(6.9314718055994531e-1f);
    e.p0 = dup2(1.0f);
    return e;
}
// 2-wide exp2 of packed pair y (scores bounded |y| < ~30: no clamp needed)
__device__ __forceinline__ uint64_t exp2_x2(uint64_t y, const ExpC& k) {
    uint64_t r   = add2(y, k.C);          // round-to-int via magic add
    uint64_t nfi = fma2(r, k.N1, k.C);    // C - r = -fi
    uint64_t f   = add2(y, nfi);          // f = y - fi, in [-0.5,0.5]
    uint64_t p   = fma2(k.p5, f, k.p4);
    p = fma2(p, f, k.p3);
    p = fma2(p, f, k.p2);
    p = fma2(p, f, k.p1);
    p = fma2(p, f, k.p0);
    uint32_t rl = (uint32_t)r, rh = (uint32_t)(r >> 32);
    uint32_t pl = (uint32_t)p, ph = (uint32_t)(p >> 32);
    // (bits(12582912+e)<<23) == e<<23 exactly (low 9 bits of magic are 0)
    return ((uint64_t)(ph + (rh << 23)) << 32) | (uint32_t)(pl + (rl << 23));
}

// ---- cp.async ---------------------------------------------------------------
__device__ __forceinline__ void cpa16(uint32_t dst, const void* src) {
    asm volatile("cp.async.cg.shared.global [%0], [%1], 16;" :: "r"(dst), "l"(src) : "memory");
}
__device__ __forceinline__ void cpa_commit() { asm volatile("cp.async.commit_group;" ::: "memory"); }
__device__ __forceinline__ void cpa_wait0()  { asm volatile("cp.async.wait_group 0;" ::: "memory"); }
__device__ __forceinline__ void cpa_wait1()  { asm volatile("cp.async.wait_group 1;" ::: "memory"); }

// prefetch [128 rows][64 half] row-major tile -> swizzled smem (128B rows)
__device__ __forceinline__ void prefetch_rc(const __half* g, uint32_t sb, int tid) {
#pragma unroll
    for (int j = 0; j < 4; j++) {
        int id = tid + j * NTHREADS;            // 1024 chunks of 16B
        int r = id >> 3, c = id & 7;
        cpa16(sb + r * 128 + ((c ^ (r & 7)) * 16), (const char*)g + id * 16);
    }
}
// prefetch V^T tile [64 d][128 keys] (row stride SEQ halfs) -> swizzled smem (256B rows)
__device__ __forceinline__ void prefetch_vt(const __half* g, uint32_t sb, int tid) {
#pragma unroll
    for (int j = 0; j < 4; j++) {
        int id = tid + j * NTHREADS;
        int d = id >> 4, c = id & 15;
        cpa16(sb + d * 256 + ((c ^ (d & 7)) * 16), (const char*)g + (d * SEQ + c * 8) * 2);
    }
}

// Q A-frags for rows 16w..16w+15, 4 k-steps
__device__ __forceinline__ void load_q_frags(uint32_t qf[4][4], uint32_t base, int w, int lane) {
#pragma unroll
    for (int kb = 0; kb < 4; kb++) {
        int row = 16 * w + (lane & 15);
        int ch = (2 * kb + (lane >> 4)) ^ (row & 7);
        ldm4(qf[kb], base + row * 128 + ch * 16);
    }
}
// scores for one 8-key block (keys 8*nbb..8*nbb+7): s[4] = Q K^T
__device__ __forceinline__ void qk_block(float s[4], const uint32_t qh[4][4],
                                         uint32_t khb, int lane, int nbb) {
    const int row = 8 * nbb + (lane & 7);
    const int m = lane >> 3;
    uint32_t a1 = row * 128 + ((m ^ (row & 7)) * 16);
    uint32_t a2 = row * 128 + (((4 + m) ^ (row & 7)) * 16);
    uint32_t kh[8];
    ldm4(kh, khb + a1); ldm4(kh + 4, khb + a2);
    s[0] = s[1] = s[2] = s[3] = 0.f;
#pragma unroll
    for (int kb = 0; kb < 4; kb++)
        mma16816(s, qh[kb], kh + 2 * kb);
}

// ---------------------------------------------------------------------------
// Preprocess: fp32 -> fp16 (scaled)
__global__ void conv_kernel(const float* __restrict__ src, __half* __restrict__ dst, float scale) {
    size_t i = (size_t)blockIdx.x * blockDim.x + threadIdx.x;   // one float4 per thread
    float4 f = ((const float4*)src)[i];
    ((uint2*)dst)[i] = make_uint2(pack_h2(f.x * scale, f.y * scale),
                                  pack_h2(f.z * scale, f.w * scale));
}
// Preprocess: V transpose + convert: v[bh][s][d] -> g_vth[bh][d][s]
__global__ void transpose_conv_v(const float* __restrict__ v) {
    __shared__ float t[32][33];
    int bh = blockIdx.z, s0 = blockIdx.x * 32, d0 = blockIdx.y * 32;
    const float* vb = v + (size_t)bh * SEQ * HDIM;
    int tx = threadIdx.x, ty = threadIdx.y;
#pragma unroll
    for (int i = 0; i < 32; i += 8)
        t[ty + i][tx] = vb[(size_t)(s0 + ty + i) * HDIM + d0 + tx];
    __syncthreads();
    size_t obase = (size_t)bh * HDIM * SEQ;
#pragma unroll
    for (int i = 0; i < 32; i += 8)
        g_vth[obase + (size_t)(d0 + ty + i) * SEQ + s0 + tx] = __float2half_rn(t[tx][ty + i]);
}

// ---------------------------------------------------------------------------
// Pass A: QK + exp -> row sums to g_inv, unnormalized P~ (fp16) to g_p.
// smem: Q 16KB + 3-stage K 48KB = 64KB, 3 CTAs/SM
__global__ __launch_bounds__(NTHREADS, 3)
void attn_sum_kernel() {
    extern __shared__ char sm[];
    const uint32_t QH = smem_u32(sm);
    const uint32_t KS = QH + 16384;
    const int tid = threadIdx.x, lane = tid & 31, w = tid >> 5;
    const int bh = blockIdx.y, q0 = blockIdx.x * QTILE;

    const __half* khg = g_kh + (size_t)bh * SEQ * HDIM;
    uint2* pb = g_p + (size_t)(bh * NQT + blockIdx.x) * NTILES * 4096 + tid;

    prefetch_rc(g_qh + ((size_t)bh * SEQ + q0) * HDIM, QH, tid);
    prefetch_rc(khg, KS, tid);
    cpa_commit();                                    // group: tile 0 (+Q)
    prefetch_rc(khg + (size_t)TKEY * HDIM, KS + 16384, tid);
    cpa_commit();                                    // group: tile 1

    const ExpC ec = make_expc();
    uint32_t qh[4][4];
    uint64_t acc01 = 0, acc23 = 0;                   // packed row-sum accumulators

    for (int kt = 0; kt < NTILES; kt++) {
        if (kt == NTILES - 1) cpa_wait0(); else cpa_wait1();
        __syncthreads();                             // single barrier per tile
        if (kt == 0) load_q_frags(qh, QH, w, lane);
        const uint32_t khb = KS + (kt % 3) * 16384;
        uint2* pt = pb + (size_t)kt * 4096;
#pragma unroll
        for (int nbb = 0; nbb < 16; nbb++) {
            float s[4];
            qk_block(s, qh, khb, lane, nbb);
            uint64_t e01 = exp2_x2(pk2(s[0], s[1]), ec);
            uint64_t e23 = exp2_x2(pk2(s[2], s[3]), ec);
            acc01 = add2(acc01, e01);
            acc23 = add2(acc23, e23);
            pt[nbb * 256] = make_uint2(pack_h2(lo2(e01), hi2(e01)),
                                       pack_h2(lo2(e23), hi2(e23)));
        }
        if (kt + 2 < NTILES) {                       // bottom prefetch into stage (kt+2)%3
            prefetch_rc(khg + (size_t)(kt + 2) * TKEY * HDIM, KS + ((kt + 2) % 3) * 16384, tid);
            cpa_commit();
        }
    }
    float sum0 = lo2(acc01) + hi2(acc01);
    float sum1 = lo2(acc23) + hi2(acc23);
    sum0 += __shfl_xor_sync(0xffffffffu, sum0, 1);
    sum0 += __shfl_xor_sync(0xffffffffu, sum0, 2);
    sum1 += __shfl_xor_sync(0xffffffffu, sum1, 1);
    sum1 += __shfl_xor_sync(0xffffffffu, sum1, 2);
    if ((lane & 3) == 0) {
        size_t base = (size_t)bh * SEQ + q0 + 16 * w + (lane >> 2);
        g_inv[base] = 1.0f / sum0;
        g_inv[base + 8] = 1.0f / sum1;
    }
}

// ---------------------------------------------------------------------------
// Pass B: load P~ from g_p, normalize -> attn, PV -> out (scaled at end).
// smem: 3-stage V 48KB, 3 CTAs/SM
__global__ __launch_bounds__(NTHREADS, 3)
void attn_main_kernel(float* __restrict__ out, float* __restrict__ attn) {
    extern __shared__ char sm[];
    const uint32_t VS = smem_u32(sm);                 // stage s: VS + (s%3)*16384
    const int tid = threadIdx.x, lane = tid & 31, w = tid >> 5;
    const int bh = blockIdx.y, q0 = blockIdx.x * QTILE;

    const __half* vthg = g_vth + (size_t)bh * HDIM * SEQ;
    const uint2* pb = g_p + (size_t)(bh * NQT + blockIdx.x) * NTILES * 4096 + tid;

    prefetch_vt(vthg, VS, tid);
    cpa_commit();                                     // tile 0
    prefetch_vt(vthg + (size_t)TKEY, VS + 16384, tid);
    cpa_commit();                                     // tile 1

    const int r = lane >> 2;
    const float inv0 = g_inv[(size_t)bh * SEQ + q0 + 16 * w + r];
    const float inv1 = g_inv[(size_t)bh * SEQ + q0 + 16 * w + r + 8];
    const uint64_t inv0p = dup2(inv0), inv1p = dup2(inv1);
    float* arow0 = attn + ((size_t)bh * SEQ + q0 + 16 * w + r) * SEQ + 2 * (lane & 3);
    float* arow1 = arow0 + (size_t)8 * SEQ;

    float o[8][4];
#pragma unroll
    for (int nb = 0; nb < 8; nb++) { o[nb][0] = o[nb][1] = o[nb][2] = o[nb][3] = 0.f; }

    const int rowm = lane & 7;
    const int m = lane >> 3;

    for (int kt = 0; kt < NTILES; kt++) {
        if (kt == NTILES - 1) cpa_wait0(); else cpa_wait1();
        __syncthreads();                              // single barrier per tile
        const uint32_t vhb = VS + (kt % 3) * 16384;
        const uint2* pt = pb + (size_t)kt * 4096;

#pragma unroll
        for (int h = 0; h < 2; h++) {
            // P~ fragments for this 64-key half (identity layout from pass A)
            uint32_t pa[4][4];
#pragma unroll
            for (int nb = 0; nb < 8; nb++) {
                int nbb = 8 * h + nb;
                uint2 pv = __ldg(&pt[nbb * 256]);
                // normalized attn write (fp32)
                float2 f01 = __half22float2(*reinterpret_cast<__half2*>(&pv.x));
                float2 f23 = __half22float2(*reinterpret_cast<__half2*>(&pv.y));
                *(uint64_t*)(arow0 + kt * TKEY + 64 * h + nb * 8) = mul2(pk2(f01.x, f01.y), inv0p);
                *(uint64_t*)(arow1 + kt * TKEY + 64 * h + nb * 8) = mul2(pk2(f23.x, f23.y), inv1p);
                pa[nb >> 1][2 * (nb & 1)]     = pv.x;
                pa[nb >> 1][2 * (nb & 1) + 1] = pv.y;
            }
            // PV over this 64-key half (unnormalized P~)
#pragma unroll
            for (int nb2 = 0; nb2 < 8; nb2++) {
                int row = 8 * nb2 + rowm;
                uint32_t vh[8];
#pragma unroll
                for (int qd = 0; qd < 2; qd++) {
                    uint32_t a = row * 256 + (((8 * h + 4 * qd + m) ^ (row & 7)) * 16);
                    ldm4(vh + 4 * qd, vhb + a);
                }
#pragma unroll
                for (int kb = 0; kb < 4; kb++)
                    mma16816(o[nb2], pa[kb], vh + 2 * kb);
            }
        }
        if (kt + 2 < NTILES) {                        // bottom prefetch into stage (kt+2)%3
            prefetch_vt(vthg + (size_t)(kt + 2) * TKEY, VS + ((kt + 2) % 3) * 16384, tid);
            cpa_commit();
        }
    }

    // write O scaled by row inverses
    float* orow0 = out + ((size_t)bh * SEQ + q0 + 16 * w + r) * HDIM + 2 * (lane & 3);
    float* orow1 = orow0 + 8 * HDIM;
#pragma unroll
    for (int nb2 = 0; nb2 < 8; nb2++) {
        *(float2*)(orow0 + nb2 * 8) = make_float2(o[nb2][0] * inv0, o[nb2][1] * inv0);
        *(float2*)(orow1 + nb2 * 8) = make_float2(o[nb2][2] * inv1, o[nb2][3] * inv1);
    }
}

// ---------------------------------------------------------------------------
extern "C" void kernel_launch(void* const* d_in, const int* in_sizes, int n_in,
                              void* d_out, int out_size) {
    const float* q = (const float*)d_in[0];
    const float* k = (const float*)d_in[1];
    const float* v = (const float*)d_in[2];
    float* out  = (float*)d_out;
    float* attn = out + (size_t)NBH * SEQ * HDIM;

    __half *qh, *kh;
    cudaGetSymbolAddress((void**)&qh, g_qh);
    cudaGetSymbolAddress((void**)&kh, g_kh);

    const int n4 = NBH * SEQ * HDIM / 4;
    conv_kernel<<<n4 / 256, 256>>>(q, qh, QSCALE);
    conv_kernel<<<n4 / 256, 256>>>(k, kh, 1.0f);
    transpose_conv_v<<<dim3(SEQ / 32, HDIM / 32, NBH), dim3(32, 8)>>>(v);

    const int smA = 65536, smB = 49152;
    cudaFuncSetAttribute(attn_sum_kernel, cudaFuncAttributeMaxDynamicSharedMemorySize, smA);
    cudaFuncSetAttribute(attn_main_kernel, cudaFuncAttributeMaxDynamicSharedMemorySize, smB);

    dim3 grid(NQT, NBH);
    attn_sum_kernel<<<grid, NTHREADS, smA>>>();
    attn_main_kernel<<<grid, NTHREADS, smB>>>(out, attn);
}

// round 17
// speedup vs baseline: 1.2083x; 1.2083x over previous
#include <cuda_runtime.h>
#include <cuda_fp16.h>
#include <cstdint>

// q,k,v: [B=4,H=16,S=2048,D=64] fp32. out = [B,H,S,D] then attn [B,H,S,S] (fp32).
#define SEQ   2048
#define HDIM  64
#define NBH   64
#define QTILE 128
#define TKEY  128
#define NTILES (SEQ/TKEY)
#define NTHREADS 256

// fold 1/temperature (1/8) and log2(e) into Q: softmax runs in exp2 domain
#define QSCALE (1.4426950408889634f / 8.0f)

// preconverted fp16 operands
__device__ __half g_qh[(size_t)NBH * SEQ * HDIM];
__device__ __half g_kh[(size_t)NBH * SEQ * HDIM];
__device__ __half g_vth[(size_t)NBH * HDIM * SEQ];   // V^T [bh][d][s]
__device__ float g_inv[(size_t)NBH * SEQ];           // per-row 1/sum

// ---------------------------------------------------------------------------
__device__ __forceinline__ uint32_t smem_u32(const void* p) {
    uint32_t a;
    asm("{ .reg .u64 t; cvta.to.shared.u64 t, %1; cvt.u32.u64 %0, t; }" : "=r"(a) : "l"(p));
    return a;
}
__device__ __forceinline__ void ldm4(uint32_t* r, uint32_t a) {
    asm volatile("ldmatrix.sync.aligned.m8n8.x4.shared.b16 {%0,%1,%2,%3}, [%4];"
                 : "=r"(r[0]), "=r"(r[1]), "=r"(r[2]), "=r"(r[3]) : "r"(a));
}
__device__ __forceinline__ void mma16816(float* c, const uint32_t* a, const uint32_t* b) {
    asm volatile("mma.sync.aligned.m16n8k16.row.col.f32.f16.f16.f32 "
                 "{%0,%1,%2,%3},{%4,%5,%6,%7},{%8,%9},{%0,%1,%2,%3};"
                 : "+f"(c[0]), "+f"(c[1]), "+f"(c[2]), "+f"(c[3])
                 : "r"(a[0]), "r"(a[1]), "r"(a[2]), "r"(a[3]), "r"(b[0]), "r"(b[1]));
}
__device__ __forceinline__ uint32_t pack_h2(float a, float b) {
    __half2 h = __floats2half2_rn(a, b);
    return *reinterpret_cast<uint32_t*>(&h);
}
// hardware exp2 on the MUFU pipe (1 issue slot; rt_SMSP=8, overlapped with fma/tensor)
__device__ __forceinline__ float ex2(float x) {
    float y; asm("ex2.approx.f32 %0, %1;" : "=f"(y) : "f"(x)); return y;
}

// ---- cp.async ---------------------------------------------------------------
__device__ __forceinline__ void cpa16(uint32_t dst, const void* src) {
    asm volatile("cp.async.cg.shared.global [%0], [%1], 16;" :: "r"(dst), "l"(src) : "memory");
}
__device__ __forceinline__ void cpa_commit() { asm volatile("cp.async.commit_group;" ::: "memory"); }
__device__ __forceinline__ void cpa_wait0()  { asm volatile("cp.async.wait_group 0;" ::: "memory"); }
__device__ __forceinline__ void cpa_wait1()  { asm volatile("cp.async.wait_group 1;" ::: "memory"); }

// prefetch [128 rows][64 half] row-major tile -> swizzled smem (128B rows)
__device__ __forceinline__ void prefetch_rc(const __half* g, uint32_t sb, int tid) {
#pragma unroll
    for (int j = 0; j < 4; j++) {
        int id = tid + j * NTHREADS;            // 1024 chunks of 16B
        int r = id >> 3, c = id & 7;
        cpa16(sb + r * 128 + ((c ^ (r & 7)) * 16), (const char*)g + id * 16);
    }
}
// prefetch V^T tile [64 d][128 keys] (row stride SEQ halfs) -> swizzled smem (256B rows)
__device__ __forceinline__ void prefetch_vt(const __half* g, uint32_t sb, int tid) {
#pragma unroll
    for (int j = 0; j < 4; j++) {
        int id = tid + j * NTHREADS;
        int d = id >> 4, c = id & 15;
        cpa16(sb + d * 256 + ((c ^ (d & 7)) * 16), (const char*)g + (d * SEQ + c * 8) * 2);
    }
}

// Q A-frags for rows 16w..16w+15, 4 k-steps
__device__ __forceinline__ void load_q_frags(uint32_t qf[4][4], uint32_t base, int w, int lane) {
#pragma unroll
    for (int kb = 0; kb < 4; kb++) {
        int row = 16 * w + (lane & 15);
        int ch = (2 * kb + (lane >> 4)) ^ (row & 7);
        ldm4(qf[kb], base + row * 128 + ch * 16);
    }
}
// scores for one 8-key block (keys 8*nbb..8*nbb+7): s[4] = Q K^T
__device__ __forceinline__ void qk_block(float s[4], const uint32_t qh[4][4],
                                         uint32_t khb, int lane, int nbb) {
    const int row = 8 * nbb + (lane & 7);
    const int m = lane >> 3;
    uint32_t a1 = row * 128 + ((m ^ (row & 7)) * 16);
    uint32_t a2 = row * 128 + (((4 + m) ^ (row & 7)) * 16);
    uint32_t kh[8];
    ldm4(kh, khb + a1); ldm4(kh + 4, khb + a2);
    s[0] = s[1] = s[2] = s[3] = 0.f;
#pragma unroll
    for (int kb = 0; kb < 4; kb++)
        mma16816(s, qh[kb], kh + 2 * kb);
}

// ---------------------------------------------------------------------------
// Preprocess: fp32 -> fp16 (scaled)
__global__ void conv_kernel(const float* __restrict__ src, __half* __restrict__ dst, float scale) {
    size_t i = (size_t)blockIdx.x * blockDim.x + threadIdx.x;   // one float4 per thread
    float4 f = ((const float4*)src)[i];
    ((uint2*)dst)[i] = make_uint2(pack_h2(f.x * scale, f.y * scale),
                                  pack_h2(f.z * scale, f.w * scale));
}
// Preprocess: V transpose + convert: v[bh][s][d] -> g_vth[bh][d][s]
__global__ void transpose_conv_v(const float* __restrict__ v) {
    __shared__ float t[32][33];
    int bh = blockIdx.z, s0 = blockIdx.x * 32, d0 = blockIdx.y * 32;
    const float* vb = v + (size_t)bh * SEQ * HDIM;
    int tx = threadIdx.x, ty = threadIdx.y;
#pragma unroll
    for (int i = 0; i < 32; i += 8)
        t[ty + i][tx] = vb[(size_t)(s0 + ty + i) * HDIM + d0 + tx];
    __syncthreads();
    size_t obase = (size_t)bh * HDIM * SEQ;
#pragma unroll
    for (int i = 0; i < 32; i += 8)
        g_vth[obase + (size_t)(d0 + ty + i) * SEQ + s0 + tx] = __float2half_rn(t[tx][ty + i]);
}

// ---------------------------------------------------------------------------
// Pass A: row sums -> g_inv.  smem: Q 16KB + 3-stage K 48KB = 64KB, 3 CTAs/SM
__global__ __launch_bounds__(NTHREADS, 3)
void attn_sum_kernel() {
    extern __shared__ char sm[];
    const uint32_t QH = smem_u32(sm);
    const uint32_t KS = QH + 16384;
    const int tid = threadIdx.x, lane = tid & 31, w = tid >> 5;
    const int bh = blockIdx.y, q0 = blockIdx.x * QTILE;

    const __half* khg = g_kh + (size_t)bh * SEQ * HDIM;
    prefetch_rc(g_qh + ((size_t)bh * SEQ + q0) * HDIM, QH, tid);
    prefetch_rc(khg, KS, tid);
    cpa_commit();                                    // group: tile 0 (+Q)
    prefetch_rc(khg + (size_t)TKEY * HDIM, KS + 16384, tid);
    cpa_commit();                                    // group: tile 1

    uint32_t qh[4][4];
    float s0a = 0.f, s0b = 0.f, s1a = 0.f, s1b = 0.f;   // 4 independent accumulators

    for (int kt = 0; kt < NTILES; kt++) {
        if (kt == NTILES - 1) cpa_wait0(); else cpa_wait1();
        __syncthreads();                             // single barrier per tile
        if (kt == 0) load_q_frags(qh, QH, w, lane);
        const uint32_t khb = KS + (kt % 3) * 16384;
#pragma unroll
        for (int nbb = 0; nbb < 16; nbb++) {
            float s[4];
            qk_block(s, qh, khb, lane, nbb);
            s0a += ex2(s[0]);
            s0b += ex2(s[1]);
            s1a += ex2(s[2]);
            s1b += ex2(s[3]);
        }
        if (kt + 2 < NTILES) {                       // bottom prefetch into stage (kt+2)%3
            prefetch_rc(khg + (size_t)(kt + 2) * TKEY * HDIM, KS + ((kt + 2) % 3) * 16384, tid);
            cpa_commit();
        }
    }
    float sum0 = s0a + s0b;
    float sum1 = s1a + s1b;
    sum0 += __shfl_xor_sync(0xffffffffu, sum0, 1);
    sum0 += __shfl_xor_sync(0xffffffffu, sum0, 2);
    sum1 += __shfl_xor_sync(0xffffffffu, sum1, 1);
    sum1 += __shfl_xor_sync(0xffffffffu, sum1, 2);
    if ((lane & 3) == 0) {
        size_t base = (size_t)bh * SEQ + q0 + 16 * w + (lane >> 2);
        g_inv[base] = 1.0f / sum0;
        g_inv[base + 8] = 1.0f / sum1;
    }
}

// ---------------------------------------------------------------------------
// Pass B: recompute scores, normalize, write attn, PV -> out.
// smem: Q 16KB + 3-stage {K 16KB + V 16KB} = 112KB, 2 CTAs/SM
__global__ __launch_bounds__(NTHREADS, 2)
void attn_main_kernel(float* __restrict__ out, float* __restrict__ attn) {
    extern __shared__ char sm[];
    const uint32_t QH = smem_u32(sm);
    const uint32_t ST = QH + 16384;                   // stage s: ST + (s%3)*32768
    const int tid = threadIdx.x, lane = tid & 31, w = tid >> 5;
    const int bh = blockIdx.y, q0 = blockIdx.x * QTILE;

    const __half* khg  = g_kh  + (size_t)bh * SEQ * HDIM;
    const __half* vthg = g_vth + (size_t)bh * HDIM * SEQ;

    prefetch_rc(g_qh + ((size_t)bh * SEQ + q0) * HDIM, QH, tid);
    prefetch_rc(khg, ST, tid);
    prefetch_vt(vthg, ST + 16384, tid);
    cpa_commit();                                     // tile 0 (+Q)
    prefetch_rc(khg + (size_t)TKEY * HDIM, ST + 32768, tid);
    prefetch_vt(vthg + (size_t)TKEY, ST + 32768 + 16384, tid);
    cpa_commit();                                     // tile 1

    uint32_t qh[4][4];
    const int r = lane >> 2;
    const float inv0 = g_inv[(size_t)bh * SEQ + q0 + 16 * w + r];
    const float inv1 = g_inv[(size_t)bh * SEQ + q0 + 16 * w + r + 8];
    float* arow0 = attn + ((size_t)bh * SEQ + q0 + 16 * w + r) * SEQ + 2 * (lane & 3);
    float* arow1 = arow0 + (size_t)8 * SEQ;

    float o[8][4];
#pragma unroll
    for (int nb = 0; nb < 8; nb++) { o[nb][0] = o[nb][1] = o[nb][2] = o[nb][3] = 0.f; }

    const int rowm = lane & 7;
    const int m = lane >> 3;

    for (int kt = 0; kt < NTILES; kt++) {
        if (kt == NTILES - 1) cpa_wait0(); else cpa_wait1();
        __syncthreads();                              // single barrier per tile
        if (kt == 0) load_q_frags(qh, QH, w, lane);
        const uint32_t khb = ST + (kt % 3) * 32768;
        const uint32_t vhb = khb + 16384;

#pragma unroll
        for (int h = 0; h < 2; h++) {
            // P fragments for this 64-key half, assembled once in mma A-frag order
            uint32_t pa[4][4];
#pragma unroll
            for (int nb = 0; nb < 8; nb++) {
                float s[4];
                qk_block(s, qh, khb, lane, 8 * h + nb);
                float p0 = ex2(s[0]) * inv0;
                float p1 = ex2(s[1]) * inv0;
                float p2 = ex2(s[2]) * inv1;
                float p3 = ex2(s[3]) * inv1;
                *(float2*)(arow0 + kt * TKEY + 64 * h + nb * 8) = make_float2(p0, p1);
                *(float2*)(arow1 + kt * TKEY + 64 * h + nb * 8) = make_float2(p2, p3);
                pa[nb >> 1][2 * (nb & 1)]     = pack_h2(p0, p1);
                pa[nb >> 1][2 * (nb & 1) + 1] = pack_h2(p2, p3);
            }
            // PV over this 64-key half
#pragma unroll
            for (int nb2 = 0; nb2 < 8; nb2++) {
                int row = 8 * nb2 + rowm;
                uint32_t vh[8];
#pragma unroll
                for (int qd = 0; qd < 2; qd++) {
                    uint32_t a = row * 256 + (((8 * h + 4 * qd + m) ^ (row & 7)) * 16);
                    ldm4(vh + 4 * qd, vhb + a);
                }
#pragma unroll
                for (int kb = 0; kb < 4; kb++)
                    mma16816(o[nb2], pa[kb], vh + 2 * kb);
            }
        }
        if (kt + 2 < NTILES) {                        // bottom prefetch into stage (kt+2)%3
            uint32_t st = ST + ((kt + 2) % 3) * 32768;
            prefetch_rc(khg + (size_t)(kt + 2) * TKEY * HDIM, st, tid);
            prefetch_vt(vthg + (size_t)(kt + 2) * TKEY, st + 16384, tid);
            cpa_commit();
        }
    }

    // write O (already normalized: P was normalized before PV)
    float* orow0 = out + ((size_t)bh * SEQ + q0 + 16 * w + r) * HDIM + 2 * (lane & 3);
    float* orow1 = orow0 + 8 * HDIM;
#pragma unroll
    for (int nb2 = 0; nb2 < 8; nb2++) {
        *(float2*)(orow0 + nb2 * 8) = make_float2(o[nb2][0], o[nb2][1]);
        *(float2*)(orow1 + nb2 * 8) = make_float2(o[nb2][2], o[nb2][3]);
    }
}

// ---------------------------------------------------------------------------
extern "C" void kernel_launch(void* const* d_in, const int* in_sizes, int n_in,
                              void* d_out, int out_size) {
    const float* q = (const float*)d_in[0];
    const float* k = (const float*)d_in[1];
    const float* v = (const float*)d_in[2];
    float* out  = (float*)d_out;
    float* attn = out + (size_t)NBH * SEQ * HDIM;

    __half *qh, *kh;
    cudaGetSymbolAddress((void**)&qh, g_qh);
    cudaGetSymbolAddress((void**)&kh, g_kh);

    const int n4 = NBH * SEQ * HDIM / 4;
    conv_kernel<<<n4 / 256, 256>>>(q, qh, QSCALE);
    conv_kernel<<<n4 / 256, 256>>>(k, kh, 1.0f);
    transpose_conv_v<<<dim3(SEQ / 32, HDIM / 32, NBH), dim3(32, 8)>>>(v);

    const int smA = 65536, smB = 114688;
    cudaFuncSetAttribute(attn_sum_kernel, cudaFuncAttributeMaxDynamicSharedMemorySize, smA);
    cudaFuncSetAttribute(attn_main_kernel, cudaFuncAttributeMaxDynamicSharedMemorySize, smB);

    dim3 grid(SEQ / QTILE, NBH);
    attn_sum_kernel<<<grid, NTHREADS, smA>>>();
    attn_main_kernel<<<grid, NTHREADS, smB>>>(out, attn);
}